// round 9
// baseline (speedup 1.0000x reference)
#include <cuda_runtime.h>
#include <cooperative_groups.h>
#include <math.h>

namespace cg = cooperative_groups;

// HawkesPointProcess: B=8, N=4096. One 8-CTA cluster per batch row; cross-CTA
// affine-scan handoff via DSMEM + cluster.sync (no global-memory flags).
//
//   A_i = e_i*(A_{i-1}+1), e_i = exp(-beta*(t_i - t_{i-1})), e_0 := 0
//   lamb_i = A_i*alpha*beta + mu
//   out[b] = sum_i log(lamb_i+1e-8)*m_i
//            - [ (t1-t0)*mu - alpha*( sum_i exp(-beta*(t1-t_i)*m_i + (1-m_i)*(-1e20)) - sum_i m_i ) ]

#define CSZ   8      // CTAs per cluster (= per batch row)
#define NT    256    // threads per CTA
#define NWARP 8
#define CHUNK 2      // CSZ*NT*CHUNK == N == 4096

__device__ __forceinline__ float softplus_fast(float x) {
    return __logf(1.0f + __expf(x));   // |x| ~ 0.3 -> rel err ~1e-6
}

__global__ __launch_bounds__(NT, 1) __cluster_dims__(CSZ, 1, 1)
void hawkes_cluster(const float* __restrict__ et,
                    const float* __restrict__ mask,
                    const float* __restrict__ t0v,
                    const float* __restrict__ t1v,
                    const float* __restrict__ mu_raw,
                    const float* __restrict__ alpha_raw,
                    const float* __restrict__ beta_raw,
                    float* __restrict__ out,
                    int N) {
    cg::cluster_group cluster = cg::this_cluster();

    const int row  = blockIdx.x / CSZ;
    const int rank = blockIdx.x % CSZ;          // cluster rank along x
    const int tid  = threadIdx.x;
    const int lane = tid & 31;
    const int warp = tid >> 5;

    const float mu    = softplus_fast(mu_raw[0]);
    const float alpha = softplus_fast(alpha_raw[0]);
    const float beta  = softplus_fast(beta_raw[0]);
    const float T1    = t1v[row];

    const float* t = et   + (size_t)row * N;
    const float* m = mask + (size_t)row * N;

    // Publication slots (read by peer CTAs through DSMEM):
    // pub[0]=G, pub[1]=H, pub[2]=comp, pub[3]=maskSum, pub[4]=logSum
    __shared__ float pub[5];
    __shared__ float sG[NWARP], sH[NWARP];
    __shared__ float rC[NWARP], rM[NWARP], rL[NWARP];
    __shared__ float sA0;

    const int idx = (rank * NT + tid) * CHUNK;   // element index in the row

    const float2 t2 = *reinterpret_cast<const float2*>(t + idx);
    const float2 m2 = *reinterpret_cast<const float2*>(m + idx);
    const float tprev = (idx == 0) ? t2.x : t[idx - 1];

    float e0 = (idx == 0) ? 0.0f : __expf(-beta * (t2.x - tprev));
    float e1 = __expf(-beta * (t2.y - t2.x));

    // Chunk-local affine transform (A_out = G*A_in + H).
    float H = fmaf(e1, e0, e1);
    float G = e0 * e1;

    // Independent partials (comp + mask), exact reference formula.
    float acc_comp = __expf(fmaf(-beta * (T1 - t2.x), m2.x, (1.0f - m2.x) * (-1e20f)))
                   + __expf(fmaf(-beta * (T1 - t2.y), m2.y, (1.0f - m2.y) * (-1e20f)));
    float acc_m = m2.x + m2.y;

    // Inclusive warp scan over (G,H), interleaved with comp/mask reductions.
    #pragma unroll
    for (int off = 1; off < 32; off <<= 1) {
        float Gp = __shfl_up_sync(0xffffffffu, G, off);
        float Hp = __shfl_up_sync(0xffffffffu, H, off);
        acc_comp += __shfl_xor_sync(0xffffffffu, acc_comp, off);
        acc_m    += __shfl_xor_sync(0xffffffffu, acc_m,    off);
        if (lane >= off) { H = fmaf(G, Hp, H); G *= Gp; }
    }
    float Gex = __shfl_up_sync(0xffffffffu, G, 1);   // lane-exclusive
    float Hex = __shfl_up_sync(0xffffffffu, H, 1);
    if (lane == 0) { Gex = 1.0f; Hex = 0.0f; }

    if (lane == 31) { sG[warp] = G; sH[warp] = H; }
    if (lane == 0)  { rC[warp] = acc_comp; rM[warp] = acc_m; }
    __syncthreads();                                          // BAR 1

    // warp0: 8-wide scan of warp aggregates + 8-wide comp/mask reduce; publish.
    if (warp == 0) {
        float g = (lane < NWARP) ? sG[lane] : 1.0f;
        float h = (lane < NWARP) ? sH[lane] : 0.0f;
        float c = (lane < NWARP) ? rC[lane] : 0.0f;
        float q = (lane < NWARP) ? rM[lane] : 0.0f;
        #pragma unroll
        for (int off = 1; off < NWARP; off <<= 1) {
            float gp = __shfl_up_sync(0xffffffffu, g, off);
            float hp = __shfl_up_sync(0xffffffffu, h, off);
            c += __shfl_xor_sync(0xffffffffu, c, off);   // xor within 8-lane group
            q += __shfl_xor_sync(0xffffffffu, q, off);
            if (lane >= off) { h = fmaf(g, hp, h); g *= gp; }
        }
        if (lane < NWARP) { sG[lane] = g; sH[lane] = h; }   // inclusive prefixes
        if (lane == NWARP - 1) {
            pub[0] = g;    // CTA aggregate G
            pub[1] = h;    // CTA aggregate H
            pub[2] = c;    // CTA comp total (lanes 0-7 all hold it)
            pub[3] = q;    // CTA mask total
        }
    }
    cluster.sync();                                           // CSYNC 1

    // Fold predecessor CTA aggregates (DSMEM reads, shuffle fold in rank order).
    float totC = 0.0f, totM = 0.0f;   // gathered by rank0's warp0 only
    if (warp == 0) {
        float Gj = 1.0f, Hj = 0.0f;
        if (lane < rank) {
            const float* pg = cluster.map_shared_rank(pub, lane);
            Gj = pg[0];
            Hj = pg[1];
        }
        float A = 0.0f;
        #pragma unroll
        for (int j = 0; j < CSZ - 1; j++) {
            float gj = __shfl_sync(0xffffffffu, Gj, j);
            float hj = __shfl_sync(0xffffffffu, Hj, j);
            if (j < rank) A = fmaf(gj, A, hj);
        }
        if (lane == 0) sA0 = A;

        if (rank == 0) {   // gather comp/mask totals from all 8 CTAs
            float c = 0.0f, q = 0.0f;
            if (lane < CSZ) {
                const float* pp = cluster.map_shared_rank(pub, lane);
                c = pp[2];
                q = pp[3];
            }
            #pragma unroll
            for (int off = 1; off < CSZ; off <<= 1) {
                c += __shfl_xor_sync(0xffffffffu, c, off);
                q += __shfl_xor_sync(0xffffffffu, q, off);
            }
            totC = c; totM = q;
        }
    }
    __syncthreads();                                          // BAR 2
    const float A0 = sA0;

    // Replay with true incoming state; single log of the lambda product.
    const float Gwp = (warp == 0) ? 1.0f : sG[warp - 1];
    const float Hwp = (warp == 0) ? 0.0f : sH[warp - 1];
    const float Aw    = fmaf(Gwp, A0, Hwp);      // state entering this warp
    const float Aprev = fmaf(Gex, Aw, Hex);      // state entering this thread

    const float ab = alpha * beta;
    float A = fmaf(e0, Aprev, e0);
    float lamb0 = fmaf(A, ab, mu) + 1e-8f;
    A = fmaf(e1, A, e1);
    float lamb1 = fmaf(A, ab, mu) + 1e-8f;
    float P = fmaf(m2.x, lamb0 - 1.0f, 1.0f) * fmaf(m2.y, lamb1 - 1.0f, 1.0f);
    float acc_log = __logf(P);

    #pragma unroll
    for (int off = 16; off > 0; off >>= 1)
        acc_log += __shfl_xor_sync(0xffffffffu, acc_log, off);
    if (lane == 0) rL[warp] = acc_log;
    __syncthreads();                                          // BAR 3

    if (warp == 0) {
        float v = (lane < NWARP) ? rL[lane] : 0.0f;
        #pragma unroll
        for (int off = 1; off < NWARP; off <<= 1)
            v += __shfl_xor_sync(0xffffffffu, v, off);
        if (lane == 0) pub[4] = v;                // CTA log total
    }
    cluster.sync();                                           // CSYNC 2

    if (rank == 0 && warp == 0) {
        float pl = 0.0f;
        if (lane < CSZ) {
            const float* pp = cluster.map_shared_rank(pub, lane);
            pl = pp[4];
        }
        #pragma unroll
        for (int off = 1; off < CSZ; off <<= 1)
            pl += __shfl_xor_sync(0xffffffffu, pl, off);
        if (lane == 0) {
            const float T0 = t0v[row];
            const float compensator = (T1 - T0) * mu - alpha * (totC - totM);
            out[row] = pl - compensator;
        }
    }
    cluster.sync();   // CSYNC 3: keep peer SMEM alive until rank0 is done
}

extern "C" void kernel_launch(void* const* d_in, const int* in_sizes, int n_in,
                              void* d_out, int out_size) {
    const float* event_times = (const float*)d_in[0];
    const float* input_mask  = (const float*)d_in[1];
    const float* t0          = (const float*)d_in[2];
    const float* t1          = (const float*)d_in[3];
    const float* mu          = (const float*)d_in[4];
    const float* alpha       = (const float*)d_in[5];
    const float* beta        = (const float*)d_in[6];
    float* out = (float*)d_out;

    const int B = in_sizes[2];       // t0 has B elements
    const int N = in_sizes[0] / B;   // 4096; CSZ*NT*CHUNK must equal N

    hawkes_cluster<<<B * CSZ, NT>>>(event_times, input_mask, t0, t1,
                                    mu, alpha, beta, out, N);
}